// round 5
// baseline (speedup 1.0000x reference)
#include <cuda_runtime.h>
#include <cuda_bf16.h>
#include <math.h>

#define BB 64
#define LL 1024
#define HH 64
#define H2 128
#define VV 32000
#define TOK 128
#define HPAD 68

// Scratch (device globals; no allocation allowed)
__device__ float  g_kall[BB * LL * HH];   // 16 MB
__device__ float4 g_meta[BB * LL];        // (rinv, 0.16*kk, dot(k_t,k_{t+1}), 0)
__device__ float  g_r2[BB * HH];

// ---- sm_103a packed-f32x2 helpers ---------------------------------------
__device__ __forceinline__ unsigned long long fma_f32x2(
        unsigned long long a, unsigned long long b, unsigned long long c) {
    unsigned long long d;
    asm("fma.rn.f32x2 %0, %1, %2, %3;" : "=l"(d) : "l"(a), "l"(b), "l"(c));
    return d;
}
__device__ __forceinline__ unsigned long long pack_f32x2(float lo, float hi) {
    unsigned long long d;
    asm("mov.b64 %0, {%1, %2};" : "=l"(d) : "f"(lo), "f"(hi));
    return d;
}
__device__ __forceinline__ float2 unpack_f32x2(unsigned long long v) {
    float lo, hi;
    asm("mov.b64 {%0, %1}, %2;" : "=f"(lo), "=f"(hi) : "l"(v));
    return make_float2(lo, hi);
}

// ---------------------------------------------------------------------------
// Kernel 1: per-token front-end (unchanged — 512 thr, 128 tokens/block)
// ---------------------------------------------------------------------------
__global__ void __launch_bounds__(512) k1_frontend(
        const int* __restrict__ seq, const float* __restrict__ embed,
        const float* __restrict__ W1, const float* __restrict__ b1,
        const float* __restrict__ W2, const float* __restrict__ b2,
        const float* __restrict__ gamma, const float* __restrict__ beta,
        const float* __restrict__ kpW) {
    extern __shared__ float sm[];
    float* h_sm  = sm;
    float* w1_sm = h_sm  + TOK * HPAD;
    float* u_sm  = w1_sm + HH * H2;
    float* w2_sm = u_sm  + TOK * H2;
    float* kp_sm = w2_sm + H2 * HH;
    float* b1s   = kp_sm + HH * HH;
    float* b2s   = b1s + H2;
    float* gsm   = b2s + HH;
    float* bsm   = gsm + HH;

    const int tid  = threadIdx.x;
    const int tok0 = blockIdx.x * TOK;

    for (int idx = tid; idx < HH * H2; idx += 512) w1_sm[idx] = W1[idx];
    for (int idx = tid; idx < H2 * HH; idx += 512) w2_sm[idx] = W2[idx];
    for (int idx = tid; idx < HH * HH; idx += 512) kp_sm[idx] = kpW[idx];
    if (tid < H2) b1s[tid] = b1[tid];
    if (tid < HH) { b2s[tid] = b2[tid]; gsm[tid] = gamma[tid]; bsm[tid] = beta[tid]; }

    #pragma unroll
    for (int k = 0; k < 16; k++) {
        int idx = tid + 512 * k;
        int t = idx >> 6, j = idx & 63;
        int row = seq[tok0 + t];
        h_sm[t * HPAD + j] = embed[row * HH + j];
    }
    __syncthreads();

    const int tt = tid >> 4;
    const int ct = tid & 15;

    // GEMM1
    {
        const int r0 = tt * 4, c0 = ct * 8;
        float acc[4][8];
        #pragma unroll
        for (int r = 0; r < 4; r++)
            #pragma unroll
            for (int c = 0; c < 8; c++) acc[r][c] = 0.f;
        #pragma unroll 2
        for (int j4 = 0; j4 < HH; j4 += 4) {
            float hv[4][4];
            #pragma unroll
            for (int r = 0; r < 4; r++)
                *(float4*)hv[r] = *(const float4*)&h_sm[(r0 + r) * HPAD + j4];
            #pragma unroll
            for (int jj = 0; jj < 4; jj++) {
                float4 wA = *(const float4*)&w1_sm[(j4 + jj) * H2 + c0];
                float4 wB = *(const float4*)&w1_sm[(j4 + jj) * H2 + c0 + 4];
                #pragma unroll
                for (int r = 0; r < 4; r++) {
                    float hvv = hv[r][jj];
                    acc[r][0] = fmaf(hvv, wA.x, acc[r][0]);
                    acc[r][1] = fmaf(hvv, wA.y, acc[r][1]);
                    acc[r][2] = fmaf(hvv, wA.z, acc[r][2]);
                    acc[r][3] = fmaf(hvv, wA.w, acc[r][3]);
                    acc[r][4] = fmaf(hvv, wB.x, acc[r][4]);
                    acc[r][5] = fmaf(hvv, wB.y, acc[r][5]);
                    acc[r][6] = fmaf(hvv, wB.z, acc[r][6]);
                    acc[r][7] = fmaf(hvv, wB.w, acc[r][7]);
                }
            }
        }
        #pragma unroll
        for (int r = 0; r < 4; r++)
            #pragma unroll
            for (int c = 0; c < 8; c++)
                u_sm[(r0 + r) * H2 + c0 + c] = fmaxf(acc[r][c] + b1s[c0 + c], 0.f);
    }
    __syncthreads();

    // GEMM2 + residual
    {
        const int r0 = tt * 4, c0 = ct * 4;
        float acc[4][4];
        #pragma unroll
        for (int r = 0; r < 4; r++)
            #pragma unroll
            for (int c = 0; c < 4; c++) acc[r][c] = 0.f;
        #pragma unroll 2
        for (int j4 = 0; j4 < H2; j4 += 4) {
            float uv[4][4];
            #pragma unroll
            for (int r = 0; r < 4; r++)
                *(float4*)uv[r] = *(const float4*)&u_sm[(r0 + r) * H2 + j4];
            #pragma unroll
            for (int jj = 0; jj < 4; jj++) {
                float4 w = *(const float4*)&w2_sm[(j4 + jj) * HH + c0];
                #pragma unroll
                for (int r = 0; r < 4; r++) {
                    float uvv = uv[r][jj];
                    acc[r][0] = fmaf(uvv, w.x, acc[r][0]);
                    acc[r][1] = fmaf(uvv, w.y, acc[r][1]);
                    acc[r][2] = fmaf(uvv, w.z, acc[r][2]);
                    acc[r][3] = fmaf(uvv, w.w, acc[r][3]);
                }
            }
        }
        #pragma unroll
        for (int r = 0; r < 4; r++)
            #pragma unroll
            for (int c = 0; c < 4; c++)
                h_sm[(r0 + r) * HPAD + c0 + c] += acc[r][c] + b2s[c0 + c];
    }
    __syncthreads();

    // LayerNorm per token
    if (tid < TOK) {
        float s = 0.f, ss = 0.f;
        #pragma unroll 8
        for (int j = 0; j < HH; j++) {
            float x = h_sm[tid * HPAD + j];
            s += x; ss += x * x;
        }
        float mu = s * (1.f / HH);
        float var = ss * (1.f / HH) - mu * mu;
        float rs = rsqrtf(var + 1e-5f);
        #pragma unroll 8
        for (int j = 0; j < HH; j++) {
            float x = h_sm[tid * HPAD + j];
            h_sm[tid * HPAD + j] = (x - mu) * rs * gsm[j] + bsm[j];
        }
    }
    __syncthreads();

    // GEMM3 -> g_kall
    {
        const int r0 = tt * 4, c0 = ct * 4;
        float acc[4][4];
        #pragma unroll
        for (int r = 0; r < 4; r++)
            #pragma unroll
            for (int c = 0; c < 4; c++) acc[r][c] = 0.f;
        #pragma unroll 2
        for (int j4 = 0; j4 < HH; j4 += 4) {
            float hv[4][4];
            #pragma unroll
            for (int r = 0; r < 4; r++)
                *(float4*)hv[r] = *(const float4*)&h_sm[(r0 + r) * HPAD + j4];
            #pragma unroll
            for (int jj = 0; jj < 4; jj++) {
                float4 w = *(const float4*)&kp_sm[(j4 + jj) * HH + c0];
                #pragma unroll
                for (int r = 0; r < 4; r++) {
                    float hvv = hv[r][jj];
                    acc[r][0] = fmaf(hvv, w.x, acc[r][0]);
                    acc[r][1] = fmaf(hvv, w.y, acc[r][1]);
                    acc[r][2] = fmaf(hvv, w.z, acc[r][2]);
                    acc[r][3] = fmaf(hvv, w.w, acc[r][3]);
                }
            }
        }
        #pragma unroll
        for (int r = 0; r < 4; r++)
            #pragma unroll
            for (int c = 0; c < 4; c++)
                g_kall[(tok0 + r0 + r) * HH + c0 + c] = acc[r][c];
    }
}

// ---------------------------------------------------------------------------
// Kernel 1b: per-(b,t) metadata: (rinv, 0.16*kk, dot(k_t,k_{t+1}))
// ---------------------------------------------------------------------------
__global__ void k1b_meta() {
    const int g    = blockIdx.x * 8 + (threadIdx.x >> 5);
    const int lane = threadIdx.x & 31;
    const int b = g >> 10, t = g & 1023;
    if (t >= LL - 1) return;
    const float* kt = g_kall + (b * LL + t) * HH;
    float2 k0 = *(const float2*)&kt[lane * 2];
    float2 k1 = *(const float2*)&kt[HH + lane * 2];
    float pkk = k0.x * k0.x + k0.y * k0.y;
    float pdt = k0.x * k1.x + k0.y * k1.y;
    #pragma unroll
    for (int off = 16; off; off >>= 1) {
        pkk += __shfl_xor_sync(0xffffffffu, pkk, off);
        pdt += __shfl_xor_sync(0xffffffffu, pdt, off);
    }
    if (lane == 0) {
        float rinv = 1.0f / fmaxf(sqrtf(pkk), 1e-12f);
        g_meta[b * LL + t] = make_float4(rinv, 0.16f * pkk, pdt, 0.f);
    }
}

// ---------------------------------------------------------------------------
// Kernel 2: 64-thread scan with
//   - M in packed f32x2 (32 u64 regs): half the FMA issue count
//   - single-chain shfl butterfly on err^2
//   - one-step deferred rank-1 update, one __syncthreads per step
// ---------------------------------------------------------------------------
__global__ void __launch_bounds__(64, 1) k2_scan(const float* __restrict__ rpW,
                                                 const float* __restrict__ rpb) {
    const int b = blockIdx.x;
    const int i = threadIdx.x;
    const int w = i >> 5;
    __shared__ __align__(16) float kbuf[4][64];
    __shared__ float wsum[2][2];
    __shared__ float rds[64];

    unsigned long long M2[32];
    #pragma unroll
    for (int j = 0; j < 32; j++) M2[j] = 0ULL;

    const float*  kb = g_kall + b * LL * HH;
    const float4* mb = g_meta + b * LL;

    float kc_cur = kb[i];
    float kc_nxt = kb[HH + i];
    float xA     = kb[2 * HH + i];
    kbuf[0][i] = kc_cur;
    kbuf[1][i] = kc_nxt;
    float4 mt = mb[0];
    float a = 0.f, gs_prev = 0.f, dot_prev = 0.f;
    int gate_prev = 0;
    __syncthreads();

    for (int t = 0; t < LL - 1; t++) {
        float xB = (t <= LL - 4) ? kb[(t + 3) * HH + i] : 0.f;
        float4 mtn = mb[t + 1];

        // vpk_t with deferred-update correction; err on the fast path
        float vpk = fmaf(gs_prev, dot_prev, a);
        float err = fmaf(-mt.x, vpk, kc_cur);          // k_i - rinv*vpk_i
        float perr = err * err;                         // single-chain reduction
        #pragma unroll
        for (int off = 16; off; off >>= 1)
            perr += __shfl_xor_sync(0xffffffffu, perr, off);
        const int p = t & 1;
        if ((i & 31) == 0) wsum[p][w] = perr;

        kbuf[(t + 2) & 3][i] = xA;                     // publish k^{t+2}

        // deferred update: M += gs_{t-1} * k^{t-1}
        if (gate_prev) {
            const ulonglong2* kp = (const ulonglong2*)kbuf[(t + 3) & 3];
            unsigned long long s2 = pack_f32x2(gs_prev, gs_prev);
            #pragma unroll
            for (int j2 = 0; j2 < 16; j2++) {
                ulonglong2 k2v = kp[j2];
                M2[2 * j2]     = fma_f32x2(s2, k2v.x, M2[2 * j2]);
                M2[2 * j2 + 1] = fma_f32x2(s2, k2v.y, M2[2 * j2 + 1]);
            }
        }

        // matvec for step t+1: a = M_{t-1} @ k^{t+1}
        {
            const ulonglong2* kn = (const ulonglong2*)kbuf[(t + 1) & 3];
            unsigned long long a0 = 0ULL, a1 = 0ULL, a2 = 0ULL, a3 = 0ULL;
            #pragma unroll
            for (int j2 = 0; j2 < 16; j2 += 2) {
                ulonglong2 kA = kn[j2];
                ulonglong2 kB = kn[j2 + 1];
                a0 = fma_f32x2(M2[2 * j2],     kA.x, a0);
                a1 = fma_f32x2(M2[2 * j2 + 1], kA.y, a1);
                a2 = fma_f32x2(M2[2 * j2 + 2], kB.x, a2);
                a3 = fma_f32x2(M2[2 * j2 + 3], kB.y, a3);
            }
            float2 f0 = unpack_f32x2(a0), f1 = unpack_f32x2(a1);
            float2 f2 = unpack_f32x2(a2), f3 = unpack_f32x2(a3);
            a = ((f0.x + f0.y) + (f1.x + f1.y)) + ((f2.x + f2.y) + (f3.x + f3.y));
        }

        __syncthreads();
        float errsum = wsum[p][0] + wsum[p][1];
        int gate = errsum >= mt.y;                     // ||err||^2 >= 0.16*||k||^2
        gs_prev = gate ? err * mt.x : 0.f;             // err_i * rinv
        gate_prev = gate;
        dot_prev = mt.z;
        mt = mtn;
        kc_cur = kc_nxt; kc_nxt = xA; xA = xB;
    }

    // read = M_{L-2} @ q (a = M_{L-3}@q; correction adds last update)
    float readv = fmaf(gs_prev, dot_prev, a);
    rds[i] = readv;
    __syncthreads();

    // r2[b][i] = read . rpW[:, i] + rpb[i]
    float acc = rpb[i];
    #pragma unroll 8
    for (int j = 0; j < 64; j++) acc = fmaf(rds[j], rpW[j * HH + i], acc);
    g_r2[b * HH + i] = acc;
}

// ---------------------------------------------------------------------------
// Kernel 3: out[b][v] = r2[b] . outW[:, v] + outb[v]
// 512 threads: 4 batch-groups x 128 v-lanes; smem transposed j-major so the
// 16 r2 operands per j come from 4 broadcast LDS.128.
// ---------------------------------------------------------------------------
__global__ void __launch_bounds__(512) k3_out(const float* __restrict__ outW,
                                              const float* __restrict__ outb,
                                              float* __restrict__ out) {
    __shared__ __align__(16) float r2t[64 * 64];   // [j][bb]
    const int tid = threadIdx.x;
    for (int idx = tid; idx < 64 * 64; idx += 512) {
        int bb = idx >> 6, j = idx & 63;
        r2t[j * 64 + bb] = g_r2[idx];              // coalesced read, scatter write
    }
    __syncthreads();

    const int vl = tid & 127;
    const int g  = tid >> 7;
    const int v  = blockIdx.x * 128 + vl;
    const int b0 = g * 16;

    float acc[16];
    #pragma unroll
    for (int bb = 0; bb < 16; bb++) acc[bb] = 0.f;

    #pragma unroll 4
    for (int j = 0; j < 64; j++) {
        float wv = outW[j * VV + v];
        const float4* r4 = (const float4*)&r2t[j * 64 + b0];
        float4 rA = r4[0], rB = r4[1], rC = r4[2], rD = r4[3];
        acc[0]  = fmaf(rA.x, wv, acc[0]);
        acc[1]  = fmaf(rA.y, wv, acc[1]);
        acc[2]  = fmaf(rA.z, wv, acc[2]);
        acc[3]  = fmaf(rA.w, wv, acc[3]);
        acc[4]  = fmaf(rB.x, wv, acc[4]);
        acc[5]  = fmaf(rB.y, wv, acc[5]);
        acc[6]  = fmaf(rB.z, wv, acc[6]);
        acc[7]  = fmaf(rB.w, wv, acc[7]);
        acc[8]  = fmaf(rC.x, wv, acc[8]);
        acc[9]  = fmaf(rC.y, wv, acc[9]);
        acc[10] = fmaf(rC.z, wv, acc[10]);
        acc[11] = fmaf(rC.w, wv, acc[11]);
        acc[12] = fmaf(rD.x, wv, acc[12]);
        acc[13] = fmaf(rD.y, wv, acc[13]);
        acc[14] = fmaf(rD.z, wv, acc[14]);
        acc[15] = fmaf(rD.w, wv, acc[15]);
    }
    float ob = outb[v];
    #pragma unroll
    for (int bb = 0; bb < 16; bb++) out[(b0 + bb) * VV + v] = acc[bb] + ob;
}

// ---------------------------------------------------------------------------
extern "C" void kernel_launch(void* const* d_in, const int* in_sizes, int n_in,
                              void* d_out, int out_size) {
    const int*   seq   = (const int*)d_in[0];
    const float* embed = (const float*)d_in[1];
    const float* W1    = (const float*)d_in[2];
    const float* b1    = (const float*)d_in[3];
    const float* W2    = (const float*)d_in[4];
    const float* b2    = (const float*)d_in[5];
    const float* gamma = (const float*)d_in[6];
    const float* beta  = (const float*)d_in[7];
    const float* kpW   = (const float*)d_in[8];
    const float* rpW   = (const float*)d_in[9];
    const float* rpb   = (const float*)d_in[10];
    const float* outW  = (const float*)d_in[11];
    const float* outb  = (const float*)d_in[12];
    float* out = (float*)d_out;

    const int smem1 = (TOK * HPAD + HH * H2 + TOK * H2 + H2 * HH + HH * HH
                       + H2 + 3 * HH) * (int)sizeof(float);
    cudaFuncSetAttribute(k1_frontend, cudaFuncAttributeMaxDynamicSharedMemorySize, smem1);

    k1_frontend<<<(BB * LL) / TOK, 512, smem1>>>(seq, embed, W1, b1, W2, b2,
                                                 gamma, beta, kpW);
    k1b_meta<<<(BB * LL) / 8, 256>>>();
    k2_scan<<<BB, 64>>>(rpW, rpb);
    k3_out<<<VV / 128, 512>>>(outW, outb, out);
}

// round 6
// speedup vs baseline: 1.2063x; 1.2063x over previous
#include <cuda_runtime.h>
#include <cuda_bf16.h>
#include <math.h>

#define BB 64
#define LL 1024
#define HH 64
#define H2 128
#define VV 32000
#define TOK 128
#define HPAD 68

// Scratch (device globals; no allocation allowed)
__device__ float  g_kall[BB * LL * HH];   // 16 MB
__device__ float4 g_meta[BB * LL];        // (rinv, 0.16*kk, dot(k_t,k_{t+1}), 0)
__device__ float  g_r2[BB * HH];

// ---------------------------------------------------------------------------
// Kernel 1: per-token front-end (unchanged — 512 thr, 128 tokens/block)
// ---------------------------------------------------------------------------
__global__ void __launch_bounds__(512) k1_frontend(
        const int* __restrict__ seq, const float* __restrict__ embed,
        const float* __restrict__ W1, const float* __restrict__ b1,
        const float* __restrict__ W2, const float* __restrict__ b2,
        const float* __restrict__ gamma, const float* __restrict__ beta,
        const float* __restrict__ kpW) {
    extern __shared__ float sm[];
    float* h_sm  = sm;
    float* w1_sm = h_sm  + TOK * HPAD;
    float* u_sm  = w1_sm + HH * H2;
    float* w2_sm = u_sm  + TOK * H2;
    float* kp_sm = w2_sm + H2 * HH;
    float* b1s   = kp_sm + HH * HH;
    float* b2s   = b1s + H2;
    float* gsm   = b2s + HH;
    float* bsm   = gsm + HH;

    const int tid  = threadIdx.x;
    const int tok0 = blockIdx.x * TOK;

    for (int idx = tid; idx < HH * H2; idx += 512) w1_sm[idx] = W1[idx];
    for (int idx = tid; idx < H2 * HH; idx += 512) w2_sm[idx] = W2[idx];
    for (int idx = tid; idx < HH * HH; idx += 512) kp_sm[idx] = kpW[idx];
    if (tid < H2) b1s[tid] = b1[tid];
    if (tid < HH) { b2s[tid] = b2[tid]; gsm[tid] = gamma[tid]; bsm[tid] = beta[tid]; }

    #pragma unroll
    for (int k = 0; k < 16; k++) {
        int idx = tid + 512 * k;
        int t = idx >> 6, j = idx & 63;
        int row = seq[tok0 + t];
        h_sm[t * HPAD + j] = embed[row * HH + j];
    }
    __syncthreads();

    const int tt = tid >> 4;
    const int ct = tid & 15;

    // GEMM1
    {
        const int r0 = tt * 4, c0 = ct * 8;
        float acc[4][8];
        #pragma unroll
        for (int r = 0; r < 4; r++)
            #pragma unroll
            for (int c = 0; c < 8; c++) acc[r][c] = 0.f;
        #pragma unroll 2
        for (int j4 = 0; j4 < HH; j4 += 4) {
            float hv[4][4];
            #pragma unroll
            for (int r = 0; r < 4; r++)
                *(float4*)hv[r] = *(const float4*)&h_sm[(r0 + r) * HPAD + j4];
            #pragma unroll
            for (int jj = 0; jj < 4; jj++) {
                float4 wA = *(const float4*)&w1_sm[(j4 + jj) * H2 + c0];
                float4 wB = *(const float4*)&w1_sm[(j4 + jj) * H2 + c0 + 4];
                #pragma unroll
                for (int r = 0; r < 4; r++) {
                    float hvv = hv[r][jj];
                    acc[r][0] = fmaf(hvv, wA.x, acc[r][0]);
                    acc[r][1] = fmaf(hvv, wA.y, acc[r][1]);
                    acc[r][2] = fmaf(hvv, wA.z, acc[r][2]);
                    acc[r][3] = fmaf(hvv, wA.w, acc[r][3]);
                    acc[r][4] = fmaf(hvv, wB.x, acc[r][4]);
                    acc[r][5] = fmaf(hvv, wB.y, acc[r][5]);
                    acc[r][6] = fmaf(hvv, wB.z, acc[r][6]);
                    acc[r][7] = fmaf(hvv, wB.w, acc[r][7]);
                }
            }
        }
        #pragma unroll
        for (int r = 0; r < 4; r++)
            #pragma unroll
            for (int c = 0; c < 8; c++)
                u_sm[(r0 + r) * H2 + c0 + c] = fmaxf(acc[r][c] + b1s[c0 + c], 0.f);
    }
    __syncthreads();

    // GEMM2 + residual
    {
        const int r0 = tt * 4, c0 = ct * 4;
        float acc[4][4];
        #pragma unroll
        for (int r = 0; r < 4; r++)
            #pragma unroll
            for (int c = 0; c < 4; c++) acc[r][c] = 0.f;
        #pragma unroll 2
        for (int j4 = 0; j4 < H2; j4 += 4) {
            float uv[4][4];
            #pragma unroll
            for (int r = 0; r < 4; r++)
                *(float4*)uv[r] = *(const float4*)&u_sm[(r0 + r) * H2 + j4];
            #pragma unroll
            for (int jj = 0; jj < 4; jj++) {
                float4 w = *(const float4*)&w2_sm[(j4 + jj) * HH + c0];
                #pragma unroll
                for (int r = 0; r < 4; r++) {
                    float uvv = uv[r][jj];
                    acc[r][0] = fmaf(uvv, w.x, acc[r][0]);
                    acc[r][1] = fmaf(uvv, w.y, acc[r][1]);
                    acc[r][2] = fmaf(uvv, w.z, acc[r][2]);
                    acc[r][3] = fmaf(uvv, w.w, acc[r][3]);
                }
            }
        }
        #pragma unroll
        for (int r = 0; r < 4; r++)
            #pragma unroll
            for (int c = 0; c < 4; c++)
                h_sm[(r0 + r) * HPAD + c0 + c] += acc[r][c] + b2s[c0 + c];
    }
    __syncthreads();

    // LayerNorm per token
    if (tid < TOK) {
        float s = 0.f, ss = 0.f;
        #pragma unroll 8
        for (int j = 0; j < HH; j++) {
            float x = h_sm[tid * HPAD + j];
            s += x; ss += x * x;
        }
        float mu = s * (1.f / HH);
        float var = ss * (1.f / HH) - mu * mu;
        float rs = rsqrtf(var + 1e-5f);
        #pragma unroll 8
        for (int j = 0; j < HH; j++) {
            float x = h_sm[tid * HPAD + j];
            h_sm[tid * HPAD + j] = (x - mu) * rs * gsm[j] + bsm[j];
        }
    }
    __syncthreads();

    // GEMM3 -> g_kall
    {
        const int r0 = tt * 4, c0 = ct * 4;
        float acc[4][4];
        #pragma unroll
        for (int r = 0; r < 4; r++)
            #pragma unroll
            for (int c = 0; c < 4; c++) acc[r][c] = 0.f;
        #pragma unroll 2
        for (int j4 = 0; j4 < HH; j4 += 4) {
            float hv[4][4];
            #pragma unroll
            for (int r = 0; r < 4; r++)
                *(float4*)hv[r] = *(const float4*)&h_sm[(r0 + r) * HPAD + j4];
            #pragma unroll
            for (int jj = 0; jj < 4; jj++) {
                float4 w = *(const float4*)&kp_sm[(j4 + jj) * HH + c0];
                #pragma unroll
                for (int r = 0; r < 4; r++) {
                    float hvv = hv[r][jj];
                    acc[r][0] = fmaf(hvv, w.x, acc[r][0]);
                    acc[r][1] = fmaf(hvv, w.y, acc[r][1]);
                    acc[r][2] = fmaf(hvv, w.z, acc[r][2]);
                    acc[r][3] = fmaf(hvv, w.w, acc[r][3]);
                }
            }
        }
        #pragma unroll
        for (int r = 0; r < 4; r++)
            #pragma unroll
            for (int c = 0; c < 4; c++)
                g_kall[(tok0 + r0 + r) * HH + c0 + c] = acc[r][c];
    }
}

// ---------------------------------------------------------------------------
// Kernel 1b: per-(b,t) metadata: (rinv, 0.16*kk, dot(k_t,k_{t+1}))
// ---------------------------------------------------------------------------
__global__ void k1b_meta() {
    const int g    = blockIdx.x * 8 + (threadIdx.x >> 5);
    const int lane = threadIdx.x & 31;
    const int b = g >> 10, t = g & 1023;
    if (t >= LL - 1) return;
    const float* kt = g_kall + (b * LL + t) * HH;
    float2 k0 = *(const float2*)&kt[lane * 2];
    float2 k1 = *(const float2*)&kt[HH + lane * 2];
    float pkk = k0.x * k0.x + k0.y * k0.y;
    float pdt = k0.x * k1.x + k0.y * k1.y;
    #pragma unroll
    for (int off = 16; off; off >>= 1) {
        pkk += __shfl_xor_sync(0xffffffffu, pkk, off);
        pdt += __shfl_xor_sync(0xffffffffu, pdt, off);
    }
    if (lane == 0) {
        float rinv = 1.0f / fmaxf(sqrtf(pkk), 1e-12f);
        g_meta[b * LL + t] = make_float4(rinv, 0.16f * pkk, pdt, 0.f);
    }
}

// ---------------------------------------------------------------------------
// Kernel 2: sequential scan, 128 threads / 4 warps.
// warp w owns rows [w*16, w*16+16); lanes (r, r+16) own the two 32-col halves
// of row i = w*16 + r. Matvec halves combine with ONE shfl.xor(16) (no smem).
// err^2 butterfly is 4 levels (16 rows per warp). One-step deferred update,
// one __syncthreads per step.
// ---------------------------------------------------------------------------
__global__ void __launch_bounds__(128, 1) k2_scan(const float* __restrict__ rpW,
                                                  const float* __restrict__ rpb) {
    const int b   = blockIdx.x;
    const int tid = threadIdx.x;
    const int w   = tid >> 5;          // warp 0..3
    const int l   = tid & 31;
    const int h   = l >> 4;            // column half 0/1
    const int r   = l & 15;
    const int i   = w * 16 + r;        // owned row
    const int c0  = h * 32;            // owned column base

    __shared__ __align__(16) float kbuf[4][64];
    __shared__ float wsum[2][4];
    __shared__ float rds[64];
    __shared__ float racc[2][64];

    float M[32];
    #pragma unroll
    for (int j = 0; j < 32; j++) M[j] = 0.f;

    const float*  kb = g_kall + b * LL * HH;
    const float4* mb = g_meta + b * LL;

    const bool pub = (h == 0);         // 64 publisher threads, element pe
    const int  pe  = i;

    if (pub) {
        kbuf[0][pe] = kb[pe];
        kbuf[1][pe] = kb[HH + pe];
    }
    float xA = pub ? kb[2 * HH + pe] : 0.f;
    float4 mt = mb[0];
    float a = 0.f, gs_prev = 0.f, dot_prev = 0.f;
    int gate_prev = 0;
    __syncthreads();

    for (int t = 0; t < LL - 1; t++) {
        float xB = (pub && t <= LL - 4) ? kb[(t + 3) * HH + pe] : 0.f;
        float4 mtn = mb[t + 1];
        const int p = t & 1;

        // 1. vpk_t (deferred correction), err_t for row i
        float kc  = kbuf[t & 3][i];
        float vpk = fmaf(gs_prev, dot_prev, a);
        float err = fmaf(-mt.x, vpk, kc);          // k_i - rinv*vpk_i

        // 2. 4-level butterfly: sum err^2 over this warp's 16 rows
        float perr = err * err;
        #pragma unroll
        for (int off = 1; off <= 8; off <<= 1)
            perr += __shfl_xor_sync(0xffffffffu, perr, off);
        if (l == 0) wsum[p][w] = perr;

        // 3. publish k^{t+2}
        if (pub) kbuf[(t + 2) & 3][pe] = xA;

        // 4. deferred update: M[i][c0..] += gs_{t-1} * k^{t-1}[c0..]
        if (gate_prev) {
            const float* kp = kbuf[(t + 3) & 3] + c0;
            #pragma unroll
            for (int j = 0; j < 32; j += 4) {
                float4 k4 = *(const float4*)&kp[j];
                M[j]     = fmaf(gs_prev, k4.x, M[j]);
                M[j + 1] = fmaf(gs_prev, k4.y, M[j + 1]);
                M[j + 2] = fmaf(gs_prev, k4.z, M[j + 2]);
                M[j + 3] = fmaf(gs_prev, k4.w, M[j + 3]);
            }
        }

        // 5. half-matvec for step t+1 and in-warp combine
        {
            const float* kn = kbuf[(t + 1) & 3] + c0;
            float v0 = 0.f, v1 = 0.f, v2 = 0.f, v3 = 0.f;
            #pragma unroll
            for (int j = 0; j < 32; j += 4) {
                float4 k4 = *(const float4*)&kn[j];
                v0 = fmaf(M[j],     k4.x, v0);
                v1 = fmaf(M[j + 1], k4.y, v1);
                v2 = fmaf(M[j + 2], k4.z, v2);
                v3 = fmaf(M[j + 3], k4.w, v3);
            }
            float ah = (v0 + v1) + (v2 + v3);
            a = ah + __shfl_xor_sync(0xffffffffu, ah, 16);   // full row sum
        }

        // 6. barrier, finalize gate_t
        __syncthreads();
        float errsum = (wsum[p][0] + wsum[p][1]) + (wsum[p][2] + wsum[p][3]);
        int gate = errsum >= mt.y;                 // ||err||^2 >= 0.16*||k||^2
        gs_prev = gate ? err * mt.x : 0.f;         // err_i * rinv
        gate_prev = gate;
        dot_prev = mt.z;
        mt = mtn;
        xA = xB;
    }

    // read_i = M_{L-2} @ q : a = M_{L-3}@q combined; correction adds last update
    {
        float readv = fmaf(gs_prev, dot_prev, a);
        if (h == 0) rds[i] = readv;
    }
    __syncthreads();

    // r2[b][col] = read . rpW[:, col] + rpb[col]; 128 threads: col=tid&63, half=tid>>6
    {
        const int col = tid & 63;
        const int hh  = tid >> 6;
        float acc = 0.f;
        #pragma unroll 8
        for (int j = 0; j < 32; j++)
            acc = fmaf(rds[hh * 32 + j], rpW[(hh * 32 + j) * HH + col], acc);
        racc[hh][col] = acc;
    }
    __syncthreads();
    if (tid < 64)
        g_r2[b * HH + tid] = racc[0][tid] + racc[1][tid] + rpb[tid];
}

// ---------------------------------------------------------------------------
// Kernel 3: out[b][v] = r2[b] . outW[:, v] + outb[v]
// (round-3 measured-best version: 512 threads, 4 batch-groups x 128 v-lanes)
// ---------------------------------------------------------------------------
__global__ void __launch_bounds__(512) k3_out(const float* __restrict__ outW,
                                              const float* __restrict__ outb,
                                              float* __restrict__ out) {
    __shared__ float r2s[64 * 64];
    const int tid = threadIdx.x;
    for (int idx = tid; idx < 64 * 64; idx += 512) r2s[idx] = g_r2[idx];
    __syncthreads();

    const int vl = tid & 127;
    const int g  = tid >> 7;           // batch group 0..3
    const int v  = blockIdx.x * 128 + vl;
    const int b0 = g * 16;

    float acc[16];
    #pragma unroll
    for (int bb = 0; bb < 16; bb++) acc[bb] = 0.f;

    #pragma unroll 8
    for (int j = 0; j < 64; j++) {
        float wv = outW[j * VV + v];
        #pragma unroll
        for (int bb = 0; bb < 16; bb++)
            acc[bb] = fmaf(r2s[(b0 + bb) * 64 + j], wv, acc[bb]);
    }
    float ob = outb[v];
    #pragma unroll
    for (int bb = 0; bb < 16; bb++) out[(b0 + bb) * VV + v] = acc[bb] + ob;
}

// ---------------------------------------------------------------------------
extern "C" void kernel_launch(void* const* d_in, const int* in_sizes, int n_in,
                              void* d_out, int out_size) {
    const int*   seq   = (const int*)d_in[0];
    const float* embed = (const float*)d_in[1];
    const float* W1    = (const float*)d_in[2];
    const float* b1    = (const float*)d_in[3];
    const float* W2    = (const float*)d_in[4];
    const float* b2    = (const float*)d_in[5];
    const float* gamma = (const float*)d_in[6];
    const float* beta  = (const float*)d_in[7];
    const float* kpW   = (const float*)d_in[8];
    const float* rpW   = (const float*)d_in[9];
    const float* rpb   = (const float*)d_in[10];
    const float* outW  = (const float*)d_in[11];
    const float* outb  = (const float*)d_in[12];
    float* out = (float*)d_out;

    const int smem1 = (TOK * HPAD + HH * H2 + TOK * H2 + H2 * HH + HH * HH
                       + H2 + 3 * HH) * (int)sizeof(float);
    cudaFuncSetAttribute(k1_frontend, cudaFuncAttributeMaxDynamicSharedMemorySize, smem1);

    k1_frontend<<<(BB * LL) / TOK, 512, smem1>>>(seq, embed, W1, b1, W2, b2,
                                                 gamma, beta, kpW);
    k1b_meta<<<(BB * LL) / 8, 256>>>();
    k2_scan<<<BB, 128>>>(rpW, rpb);
    k3_out<<<VV / 128, 512>>>(outW, outb, out);
}

// round 8
// speedup vs baseline: 1.3586x; 1.1263x over previous
#include <cuda_runtime.h>
#include <cuda_bf16.h>
#include <math.h>

#define BB 64
#define LL 1024
#define HH 64
#define H2 128
#define VV 32000
#define TOK 128
#define HPAD 68

// Scratch (device globals; no allocation allowed)
__device__ float  g_kall[BB * LL * HH];   // 16 MB
__device__ float4 g_meta[BB * LL];        // (rinv, 0.16*kk, dot(k_t,k_{t+1}), dot(k_t,k_{t+2}))
__device__ float  g_r2[BB * HH];

// ---------------------------------------------------------------------------
// Kernel 1: per-token front-end (measured-best r2 config: 512 thr, 128 tok)
// ---------------------------------------------------------------------------
__global__ void __launch_bounds__(512) k1_frontend(
        const int* __restrict__ seq, const float* __restrict__ embed,
        const float* __restrict__ W1, const float* __restrict__ b1,
        const float* __restrict__ W2, const float* __restrict__ b2,
        const float* __restrict__ gamma, const float* __restrict__ beta,
        const float* __restrict__ kpW) {
    extern __shared__ float sm[];
    float* h_sm  = sm;
    float* w1_sm = h_sm  + TOK * HPAD;
    float* u_sm  = w1_sm + HH * H2;
    float* w2_sm = u_sm  + TOK * H2;
    float* kp_sm = w2_sm + H2 * HH;
    float* b1s   = kp_sm + HH * HH;
    float* b2s   = b1s + H2;
    float* gsm   = b2s + HH;
    float* bsm   = gsm + HH;

    const int tid  = threadIdx.x;
    const int tok0 = blockIdx.x * TOK;

    for (int idx = tid; idx < HH * H2; idx += 512) w1_sm[idx] = W1[idx];
    for (int idx = tid; idx < H2 * HH; idx += 512) w2_sm[idx] = W2[idx];
    for (int idx = tid; idx < HH * HH; idx += 512) kp_sm[idx] = kpW[idx];
    if (tid < H2) b1s[tid] = b1[tid];
    if (tid < HH) { b2s[tid] = b2[tid]; gsm[tid] = gamma[tid]; bsm[tid] = beta[tid]; }

    #pragma unroll
    for (int k = 0; k < 16; k++) {
        int idx = tid + 512 * k;
        int t = idx >> 6, j = idx & 63;
        int row = seq[tok0 + t];
        h_sm[t * HPAD + j] = embed[row * HH + j];
    }
    __syncthreads();

    const int tt = tid >> 4;
    const int ct = tid & 15;

    // GEMM1
    {
        const int r0 = tt * 4, c0 = ct * 8;
        float acc[4][8];
        #pragma unroll
        for (int r = 0; r < 4; r++)
            #pragma unroll
            for (int c = 0; c < 8; c++) acc[r][c] = 0.f;
        #pragma unroll 2
        for (int j4 = 0; j4 < HH; j4 += 4) {
            float hv[4][4];
            #pragma unroll
            for (int r = 0; r < 4; r++)
                *(float4*)hv[r] = *(const float4*)&h_sm[(r0 + r) * HPAD + j4];
            #pragma unroll
            for (int jj = 0; jj < 4; jj++) {
                float4 wA = *(const float4*)&w1_sm[(j4 + jj) * H2 + c0];
                float4 wB = *(const float4*)&w1_sm[(j4 + jj) * H2 + c0 + 4];
                #pragma unroll
                for (int r = 0; r < 4; r++) {
                    float hvv = hv[r][jj];
                    acc[r][0] = fmaf(hvv, wA.x, acc[r][0]);
                    acc[r][1] = fmaf(hvv, wA.y, acc[r][1]);
                    acc[r][2] = fmaf(hvv, wA.z, acc[r][2]);
                    acc[r][3] = fmaf(hvv, wA.w, acc[r][3]);
                    acc[r][4] = fmaf(hvv, wB.x, acc[r][4]);
                    acc[r][5] = fmaf(hvv, wB.y, acc[r][5]);
                    acc[r][6] = fmaf(hvv, wB.z, acc[r][6]);
                    acc[r][7] = fmaf(hvv, wB.w, acc[r][7]);
                }
            }
        }
        #pragma unroll
        for (int r = 0; r < 4; r++)
            #pragma unroll
            for (int c = 0; c < 8; c++)
                u_sm[(r0 + r) * H2 + c0 + c] = fmaxf(acc[r][c] + b1s[c0 + c], 0.f);
    }
    __syncthreads();

    // GEMM2 + residual
    {
        const int r0 = tt * 4, c0 = ct * 4;
        float acc[4][4];
        #pragma unroll
        for (int r = 0; r < 4; r++)
            #pragma unroll
            for (int c = 0; c < 4; c++) acc[r][c] = 0.f;
        #pragma unroll 2
        for (int j4 = 0; j4 < H2; j4 += 4) {
            float uv[4][4];
            #pragma unroll
            for (int r = 0; r < 4; r++)
                *(float4*)uv[r] = *(const float4*)&u_sm[(r0 + r) * H2 + j4];
            #pragma unroll
            for (int jj = 0; jj < 4; jj++) {
                float4 w = *(const float4*)&w2_sm[(j4 + jj) * HH + c0];
                #pragma unroll
                for (int r = 0; r < 4; r++) {
                    float uvv = uv[r][jj];
                    acc[r][0] = fmaf(uvv, w.x, acc[r][0]);
                    acc[r][1] = fmaf(uvv, w.y, acc[r][1]);
                    acc[r][2] = fmaf(uvv, w.z, acc[r][2]);
                    acc[r][3] = fmaf(uvv, w.w, acc[r][3]);
                }
            }
        }
        #pragma unroll
        for (int r = 0; r < 4; r++)
            #pragma unroll
            for (int c = 0; c < 4; c++)
                h_sm[(r0 + r) * HPAD + c0 + c] += acc[r][c] + b2s[c0 + c];
    }
    __syncthreads();

    // LayerNorm per token
    if (tid < TOK) {
        float s = 0.f, ss = 0.f;
        #pragma unroll 8
        for (int j = 0; j < HH; j++) {
            float x = h_sm[tid * HPAD + j];
            s += x; ss += x * x;
        }
        float mu = s * (1.f / HH);
        float var = ss * (1.f / HH) - mu * mu;
        float rs = rsqrtf(var + 1e-5f);
        #pragma unroll 8
        for (int j = 0; j < HH; j++) {
            float x = h_sm[tid * HPAD + j];
            h_sm[tid * HPAD + j] = (x - mu) * rs * gsm[j] + bsm[j];
        }
    }
    __syncthreads();

    // GEMM3 -> g_kall
    {
        const int r0 = tt * 4, c0 = ct * 4;
        float acc[4][4];
        #pragma unroll
        for (int r = 0; r < 4; r++)
            #pragma unroll
            for (int c = 0; c < 4; c++) acc[r][c] = 0.f;
        #pragma unroll 2
        for (int j4 = 0; j4 < HH; j4 += 4) {
            float hv[4][4];
            #pragma unroll
            for (int r = 0; r < 4; r++)
                *(float4*)hv[r] = *(const float4*)&h_sm[(r0 + r) * HPAD + j4];
            #pragma unroll
            for (int jj = 0; jj < 4; jj++) {
                float4 w = *(const float4*)&kp_sm[(j4 + jj) * HH + c0];
                #pragma unroll
                for (int r = 0; r < 4; r++) {
                    float hvv = hv[r][jj];
                    acc[r][0] = fmaf(hvv, w.x, acc[r][0]);
                    acc[r][1] = fmaf(hvv, w.y, acc[r][1]);
                    acc[r][2] = fmaf(hvv, w.z, acc[r][2]);
                    acc[r][3] = fmaf(hvv, w.w, acc[r][3]);
                }
            }
        }
        #pragma unroll
        for (int r = 0; r < 4; r++)
            #pragma unroll
            for (int c = 0; c < 4; c++)
                g_kall[(tok0 + r0 + r) * HH + c0 + c] = acc[r][c];
    }
}

// ---------------------------------------------------------------------------
// Kernel 1b: per-(b,t) metadata: (rinv, 0.16*kk, dot(k_t,k_{t+1}), dot(k_t,k_{t+2}))
// ---------------------------------------------------------------------------
__global__ void k1b_meta() {
    const int g    = blockIdx.x * 8 + (threadIdx.x >> 5);
    const int lane = threadIdx.x & 31;
    const int b = g >> 10, t = g & 1023;
    if (t >= LL - 1) return;
    const float* kt = g_kall + (b * LL + t) * HH;
    float2 k0 = *(const float2*)&kt[lane * 2];
    float2 k1 = *(const float2*)&kt[HH + lane * 2];
    float2 k2v = make_float2(0.f, 0.f);
    if (t + 2 <= LL - 1) k2v = *(const float2*)&kt[2 * HH + lane * 2];
    float pkk = k0.x * k0.x + k0.y * k0.y;
    float pd1 = k0.x * k1.x + k0.y * k1.y;
    float pd2 = k0.x * k2v.x + k0.y * k2v.y;
    #pragma unroll
    for (int off = 16; off; off >>= 1) {
        pkk += __shfl_xor_sync(0xffffffffu, pkk, off);
        pd1 += __shfl_xor_sync(0xffffffffu, pd1, off);
        pd2 += __shfl_xor_sync(0xffffffffu, pd2, off);
    }
    if (lane == 0) {
        float rinv = 1.0f / fmaxf(sqrtf(pkk), 1e-12f);
        g_meta[b * LL + t] = make_float4(rinv, 0.16f * pkk, pd1, pd2);
    }
}

// ---------------------------------------------------------------------------
// Kernel 2: 64-thread scan, LAG-2 pipeline.
// At iter t: M holds M_{t-3}; vpk_t = a + s_{t-2}*D(t-2,t) + s_{t-1}*D(t-1,t)
// where a = M_{t-3}@k_t (matvec from iter t-1). Then: apply update s_{t-2}
// (gate known a full iteration earlier -> off the critical chain), matvec
// M_{t-2}@k^{t+1}. The loop-carried chain is only corr->err->butterfly->BAR.
// ---------------------------------------------------------------------------
__global__ void __launch_bounds__(64, 1) k2_scan(const float* __restrict__ rpW,
                                                 const float* __restrict__ rpb) {
    const int b = blockIdx.x;
    const int i = threadIdx.x;
    const int w = i >> 5;
    __shared__ __align__(16) float kbuf[8][64];
    __shared__ float wsum[2][2];
    __shared__ float rds[64];

    float M[64];
    #pragma unroll
    for (int j = 0; j < 64; j++) M[j] = 0.f;

    const float*  kb = g_kall + b * LL * HH;
    const float4* mb = g_meta + b * LL;

    float kc_cur = kb[i];            // k^0_i
    float kc_nxt = kb[HH + i];       // k^1_i
    float xA     = kb[2 * HH + i];   // k^2_i (published at iter 0)
    kbuf[0][i] = kc_cur;
    kbuf[1][i] = kc_nxt;
    float4 mt = mb[0];
    float a = 0.f;
    float gs1 = 0.f, gs2 = 0.f;      // s_{t-1}, s_{t-2} (per-thread err_i*rinv, gated)
    int   g1 = 0, g2 = 0;            // gate flags (block-uniform)
    float d1 = 0.f, d2 = 0.f, w_prev = 0.f;
    __syncthreads();

    for (int t = 0; t < LL - 1; t++) {
        float xB = (t <= LL - 4) ? kb[(t + 3) * HH + i] : 0.f;
        float4 mtn = mb[t + 1];
        const int p = t & 1;

        // 1. vpk_t = M_{t-1}@k_t via lag-2 base + two corrections (critical chain)
        float vpk = fmaf(gs2, d2, fmaf(gs1, d1, a));
        float err = fmaf(-mt.x, vpk, kc_cur);       // k_i - rinv*vpk_i
        float s   = err * mt.x;                     // candidate update scalar
        float perr = err * err;
        #pragma unroll
        for (int off = 16; off; off >>= 1)
            perr += __shfl_xor_sync(0xffffffffu, perr, off);
        if ((i & 31) == 0) wsum[p][w] = perr;

        kbuf[(t + 2) & 7][i] = xA;                  // publish k^{t+2}

        // 2. apply update s_{t-2}: M_{t-3} -> M_{t-2} (one-iteration-old gate)
        if (g2) {
            const float* kp = kbuf[(t - 2) & 7];
            #pragma unroll
            for (int j = 0; j < 64; j += 4) {
                float4 k4 = *(const float4*)&kp[j];
                M[j]     = fmaf(gs2, k4.x, M[j]);
                M[j + 1] = fmaf(gs2, k4.y, M[j + 1]);
                M[j + 2] = fmaf(gs2, k4.z, M[j + 2]);
                M[j + 3] = fmaf(gs2, k4.w, M[j + 3]);
            }
        }

        // 3. matvec: a = M_{t-2} @ k^{t+1} (independent of gate_{t-1}, gate_t)
        {
            const float* kn = kbuf[(t + 1) & 7];
            float v0 = 0.f, v1 = 0.f, v2 = 0.f, v3 = 0.f;
            #pragma unroll
            for (int j = 0; j < 64; j += 4) {
                float4 k4 = *(const float4*)&kn[j];
                v0 = fmaf(M[j],     k4.x, v0);
                v1 = fmaf(M[j + 1], k4.y, v1);
                v2 = fmaf(M[j + 2], k4.z, v2);
                v3 = fmaf(M[j + 3], k4.w, v3);
            }
            a = (v0 + v1) + (v2 + v3);
        }

        // 4. barrier, finalize gate_t, shift the pipeline
        __syncthreads();
        float errsum = wsum[p][0] + wsum[p][1];
        int gate = errsum >= mt.y;                  // ||err||^2 >= 0.16*||k||^2
        gs2 = gs1;  g2 = g1;
        gs1 = gate ? s : 0.f;  g1 = gate;
        d2 = w_prev;            // D(t-1, t+1) = meta[t-1].w  (lag-2 dot)
        d1 = mt.z;              // D(t,   t+1) = meta[t].z
        w_prev = mt.w;
        mt = mtn;
        kc_cur = kc_nxt; kc_nxt = xA; xA = xB;
    }

    // read = M_{L-2}@q = a + s_{L-3}*D(L-3,L-1) + s_{L-2}*D(L-2,L-1)
    // (a = M_{L-4}@q from the last matvec; gs/d registers hold exactly these)
    float readv = fmaf(gs2, d2, fmaf(gs1, d1, a));
    rds[i] = readv;
    __syncthreads();

    // r2[b][i] = read . rpW[:, i] + rpb[i]
    float acc = rpb[i];
    #pragma unroll 8
    for (int j = 0; j < 64; j++) acc = fmaf(rds[j], rpW[j * HH + i], acc);
    g_r2[b * HH + i] = acc;
}

// ---------------------------------------------------------------------------
// Kernel 3: out[b][v] = r2[b] . outW[:, v] + outb[v]
// launch_bounds(512, 2): force 2 blocks/SM (regs <= 64) to double MLP.
// ---------------------------------------------------------------------------
__global__ void __launch_bounds__(512, 2) k3_out(const float* __restrict__ outW,
                                                 const float* __restrict__ outb,
                                                 float* __restrict__ out) {
    __shared__ float r2s[64 * 64];
    const int tid = threadIdx.x;
    for (int idx = tid; idx < 64 * 64; idx += 512) r2s[idx] = g_r2[idx];
    __syncthreads();

    const int vl = tid & 127;
    const int g  = tid >> 7;           // batch group 0..3
    const int v  = blockIdx.x * 128 + vl;
    const int b0 = g * 16;

    float acc[16];
    #pragma unroll
    for (int bb = 0; bb < 16; bb++) acc[bb] = 0.f;

    #pragma unroll 8
    for (int j = 0; j < 64; j++) {
        float wv = outW[j * VV + v];
        #pragma unroll
        for (int bb = 0; bb < 16; bb++)
            acc[bb] = fmaf(r2s[(b0 + bb) * 64 + j], wv, acc[bb]);
    }
    float ob = outb[v];
    #pragma unroll
    for (int bb = 0; bb < 16; bb++) out[(b0 + bb) * VV + v] = acc[bb] + ob;
}

// ---------------------------------------------------------------------------
extern "C" void kernel_launch(void* const* d_in, const int* in_sizes, int n_in,
                              void* d_out, int out_size) {
    const int*   seq   = (const int*)d_in[0];
    const float* embed = (const float*)d_in[1];
    const float* W1    = (const float*)d_in[2];
    const float* b1    = (const float*)d_in[3];
    const float* W2    = (const float*)d_in[4];
    const float* b2    = (const float*)d_in[5];
    const float* gamma = (const float*)d_in[6];
    const float* beta  = (const float*)d_in[7];
    const float* kpW   = (const float*)d_in[8];
    const float* rpW   = (const float*)d_in[9];
    const float* rpb   = (const float*)d_in[10];
    const float* outW  = (const float*)d_in[11];
    const float* outb  = (const float*)d_in[12];
    float* out = (float*)d_out;

    const int smem1 = (TOK * HPAD + HH * H2 + TOK * H2 + H2 * HH + HH * HH
                       + H2 + 3 * HH) * (int)sizeof(float);
    cudaFuncSetAttribute(k1_frontend, cudaFuncAttributeMaxDynamicSharedMemorySize, smem1);
    cudaFuncSetAttribute(k1_frontend, cudaFuncAttributePreferredSharedMemoryCarveout, 100);

    k1_frontend<<<(BB * LL) / TOK, 512, smem1>>>(seq, embed, W1, b1, W2, b2,
                                                 gamma, beta, kpW);
    k1b_meta<<<(BB * LL) / 8, 256>>>();
    k2_scan<<<BB, 64>>>(rpW, rpb);
    k3_out<<<VV / 128, 512>>>(outW, outb, out);
}